// round 5
// baseline (speedup 1.0000x reference)
#include <cuda_runtime.h>
#include <cuda_bf16.h>
#include <cstdint>

// Problem constants
#define BB 512      // batch
#define TT 365      // time steps
#define CC 10       // channels
#define PP 64       // prototypes
#define KK 3650     // T*C
#define KREAL 4015  // 3650 + 365
#define NKS 32      // K-split chunks (128 deep each)

// Output layout (float32, concatenated in reference return order)
#define O_OUTSEQ 0
#define O_INSEQ  1868800
#define O_DIST   3737600
#define O_IDX    3770368
#define O_LABEL  3770880
#define O_MASK   3771392

// ---------------- scratch (device globals; no allocation allowed) ----------
__device__ float g_part[NKS * BB * PP];     // K-split partials [ks][b][p] (4 MB)
__device__ float g_x2p[BB * NKS];           // x2 partials [b][ks]

// ---------------- packed f32x2 helpers -------------------------------------
__device__ __forceinline__ void fma2(unsigned long long& d,
                                     unsigned long long a,
                                     unsigned long long b) {
    asm("fma.rn.f32x2 %0, %1, %2, %0;" : "+l"(d) : "l"(a), "l"(b));
}
__device__ __forceinline__ unsigned long long pack2(float x) {
    unsigned long long r;
    asm("mov.b64 %0, {%1, %1};" : "=l"(r) : "f"(x));
    return r;
}
__device__ __forceinline__ unsigned long long packab(float lo, float hi) {
    unsigned long long r;
    asm("mov.b64 %0, {%1, %2};" : "=l"(r) : "f"(lo), "f"(hi));
    return r;
}

// ---------------- fused GEMM ------------------------------------------------
// Virtual A[b,k] = mask[b,k/10]*x[b,k] (k<KK); mask[b,k-KK] (KK<=k<KREAL); 0
// Virtual W^T[k][p] = -2*proto[p,k] (k<KK); sum_c proto[p,t,c]^2 (tail); 0
// Side effects: raw x tile -> O_INSEQ, mask tail -> O_MASK (each covered once)
// part[ks][b][p] += A*W over 128-deep chunk; x2p[b][ks] = sum A^2 (k<KK).
// BM=128, BN=64, 4 halves of 32, 256 threads, register double-buffering.
__global__ void __launch_bounds__(256, 2) k_gemm(const float* __restrict__ x,
                                                 const float* __restrict__ mask,
                                                 const float* __restrict__ proto,
                                                 float* __restrict__ out) {
    __shared__ float As[128][33];   // [b_local][k_local]  16.9 KB
    __shared__ float Ws[64][33];    // [p][k_local]         8.4 KB
    int ks = blockIdx.x;            // 0..31
    int k0 = ks * 128;
    int b0 = blockIdx.y * 128;
    int tid = threadIdx.x;
    int warp = tid >> 5;            // 0..7
    int lane = tid & 31;

    unsigned long long acc2[4][4];
    #pragma unroll
    for (int j = 0; j < 4; j++)
        #pragma unroll
        for (int i = 0; i < 4; i++) acc2[j][i] = 0ull;
    float x2a[4] = {0.f, 0.f, 0.f, 0.f};

    float ax[16];   // A prefetch: rows warp+8i, col lane
    float aw[8];    // W prefetch: p = 8i+warp, col lane

    // ---- prefetch one 32-deep half into registers (+ fused copies) --------
    auto prefetch = [&](int h) {
        int k = k0 + h * 32 + lane;
        bool isx = (k < KK);
        bool ism = (!isx) && (k < KREAL);
        int t = isx ? (k / CC) : (k - KK);
        #pragma unroll
        for (int i = 0; i < 16; i++) {
            int b = b0 + warp + i * 8;
            float v = 0.0f;
            if (isx) {
                float xv = x[b * KK + k];
                float m = __ldg(&mask[b * TT + t]);
                v = xv * m;
                out[O_INSEQ + b * KK + k] = xv;      // fused input_seq copy
            } else if (ism) {
                v = __ldg(&mask[b * TT + t]);
                out[O_MASK + b * TT + t] = v;        // fused mask copy
            }
            ax[i] = v;
        }
        #pragma unroll
        for (int i = 0; i < 8; i++) {
            int p = i * 8 + warp;
            float wv = 0.0f;
            if (isx) {
                wv = -2.0f * proto[p * KK + k];
            } else if (ism) {
                float s = 0.0f;
                const float* pb = proto + p * KK + t * CC;
                #pragma unroll
                for (int c = 0; c < CC; c++) { float q = pb[c]; s += q * q; }
                wv = s;
            }
            aw[i] = wv;
        }
    };

    prefetch(0);
    for (int h = 0; h < 4; h++) {
        if (h) __syncthreads();              // readers of previous half done
        #pragma unroll
        for (int i = 0; i < 16; i++) As[warp + i * 8][lane] = ax[i];
        #pragma unroll
        for (int i = 0; i < 8; i++)  Ws[i * 8 + warp][lane] = aw[i];
        __syncthreads();
        if (h < 3) prefetch(h + 1);          // gmem loads overlap compute

        int kbase = k0 + h * 32;
        #pragma unroll 8
        for (int kk = 0; kk < 32; kk++) {
            float a[4];
            #pragma unroll
            for (int j = 0; j < 4; j++) a[j] = As[lane + 32 * j][kk];
            // warp-uniform broadcast reads of W row
            float w0 = Ws[warp * 8 + 0][kk], w1 = Ws[warp * 8 + 1][kk];
            float w2 = Ws[warp * 8 + 2][kk], w3 = Ws[warp * 8 + 3][kk];
            float w4 = Ws[warp * 8 + 4][kk], w5 = Ws[warp * 8 + 5][kk];
            float w6 = Ws[warp * 8 + 6][kk], w7 = Ws[warp * 8 + 7][kk];
            unsigned long long w01 = packab(w0, w1), w23 = packab(w2, w3);
            unsigned long long w45 = packab(w4, w5), w67 = packab(w6, w7);
            #pragma unroll
            for (int j = 0; j < 4; j++) {
                unsigned long long aj = pack2(a[j]);
                fma2(acc2[j][0], aj, w01);
                fma2(acc2[j][1], aj, w23);
                fma2(acc2[j][2], aj, w45);
                fma2(acc2[j][3], aj, w67);
            }
            if (warp == 0 && (kbase + kk) < KK) {
                #pragma unroll
                for (int j = 0; j < 4; j++) x2a[j] += a[j] * a[j];
            }
        }
    }

    // ---- write partials ---------------------------------------------------
    #pragma unroll
    for (int j = 0; j < 4; j++) {
        int b = b0 + lane + 32 * j;
        float2 p0v = *reinterpret_cast<float2*>(&acc2[j][0]);
        float2 p1v = *reinterpret_cast<float2*>(&acc2[j][1]);
        float2 p2v = *reinterpret_cast<float2*>(&acc2[j][2]);
        float2 p3v = *reinterpret_cast<float2*>(&acc2[j][3]);
        float* dst = &g_part[(ks * BB + b) * PP + warp * 8];
        *reinterpret_cast<float4*>(dst)     = make_float4(p0v.x, p0v.y, p1v.x, p1v.y);
        *reinterpret_cast<float4*>(dst + 4) = make_float4(p2v.x, p2v.y, p3v.x, p3v.y);
    }
    if (warp == 0) {
        #pragma unroll
        for (int j = 0; j < 4; j++)
            g_x2p[(b0 + lane + 32 * j) * NKS + ks] = x2a[j];
    }
}

// ---------------- reduce + argmin + dist/idx/label + gather ----------------
__global__ void __launch_bounds__(256) k_reduce(const int* __restrict__ label,
                                                const float* __restrict__ proto,
                                                float* __restrict__ out) {
    __shared__ float sp[4][64];
    __shared__ float sx0;
    __shared__ float sv[64];
    __shared__ int si[64];
    __shared__ int sidx;
    int b = blockIdx.x;
    int tid = threadIdx.x;
    int pp = tid & 63;
    int g = tid >> 6;                  // 0..3: each sums 8 ks chunks

    float acc = 0.0f;
    #pragma unroll
    for (int i = 0; i < 8; i++)
        acc += g_part[((g * 8 + i) * BB + b) * PP + pp];
    sp[g][pp] = acc;
    __syncthreads();

    if (tid < 32) {                    // x2 = sum of 32 chunk partials
        float v = g_x2p[b * NKS + tid];
        #pragma unroll
        for (int s = 16; s > 0; s >>= 1)
            v += __shfl_xor_sync(0xffffffff, v, s);
        if (tid == 0) sx0 = v;
    }
    __syncthreads();

    if (tid < 64) {
        float tot = sp[0][pp] + sp[1][pp] + sp[2][pp] + sp[3][pp] + sx0;
        out[O_DIST + b * PP + pp] = tot;
        sv[pp] = tot;
        si[pp] = pp;
    }
    __syncthreads();
    for (int s = 32; s > 0; s >>= 1) {
        if (tid < s) {
            float ov = sv[tid + s];
            int oi = si[tid + s];
            if (ov < sv[tid] || (ov == sv[tid] && oi < si[tid])) {
                sv[tid] = ov;
                si[tid] = oi;
            }
        }
        __syncthreads();
    }
    if (tid == 0) {
        sidx = si[0];
        out[O_IDX + b] = (float)si[0];
        out[O_LABEL + b] = (float)label[b];
    }
    __syncthreads();

    // gather selected prototype row (rows 8B-aligned: KK*4 = 14600B)
    int idx = sidx;
    const float2* src = reinterpret_cast<const float2*>(proto + idx * KK);
    float2* d0 = reinterpret_cast<float2*>(out + O_OUTSEQ + b * KK);
    #pragma unroll 4
    for (int i = tid; i < KK / 2; i += 256)
        d0[i] = src[i];
}

// ---------------- launcher --------------------------------------------------
extern "C" void kernel_launch(void* const* d_in, const int* in_sizes, int n_in,
                              void* d_out, int out_size) {
    const float* x     = (const float*)d_in[0];  // [B,T,C]
    const float* mask  = (const float*)d_in[1];  // [B,T]
    const int*   label = (const int*)d_in[2];    // [B]
    const float* proto = (const float*)d_in[3];  // [P,T,C]
    float* out = (float*)d_out;

    k_gemm<<<dim3(NKS, 4), 256>>>(x, mask, proto, out);
    k_reduce<<<BB, 256>>>(label, proto, out);
}

// round 6
// speedup vs baseline: 1.2923x; 1.2923x over previous
#include <cuda_runtime.h>
#include <cuda_bf16.h>
#include <cstdint>

// Problem constants
#define BB 512      // batch
#define TT 365      // time steps
#define CC 10       // channels
#define PP 64       // prototypes
#define KK 3650     // T*C
#define KREAL 4015  // 3650 + 365
#define NKS 64      // K-split chunks (64 deep each)

// Output layout (float32, concatenated in reference return order)
#define O_OUTSEQ 0
#define O_INSEQ  1868800
#define O_DIST   3737600
#define O_IDX    3770368
#define O_LABEL  3770880
#define O_MASK   3771392

// ---------------- scratch (device globals; no allocation allowed) ----------
__device__ float g_part[NKS * BB * PP];     // K-split partials [ks][b][p] (8 MB)
__device__ float g_x2p[BB * NKS];           // x2 partials [b][ks]

// ---------------- packed f32x2 helpers -------------------------------------
__device__ __forceinline__ void fma2(unsigned long long& d,
                                     unsigned long long a,
                                     unsigned long long b) {
    asm("fma.rn.f32x2 %0, %1, %2, %0;" : "+l"(d) : "l"(a), "l"(b));
}
__device__ __forceinline__ unsigned long long pack2(float x) {
    unsigned long long r;
    asm("mov.b64 %0, {%1, %1};" : "=l"(r) : "f"(x));
    return r;
}

// ---------------- fused GEMM ------------------------------------------------
// Virtual A[b,k] = mask[b,k/10]*x[b,k] (k<KK); mask[b,k-KK] (KK<=k<KREAL); 0
// Virtual W^T[k][p] = -2*proto[p,k] (k<KK); sum_c proto[p,t,c]^2 (tail); 0
// part[ks][b][p] = sum over 64-deep chunk; x2p[b][ks] = sum A^2 (k<KK).
// BM=128, BN=64, 2 halves of 32, 256 threads, 4x8 f32x2 register tile.
__global__ void __launch_bounds__(256, 3) k_gemm(const float* __restrict__ x,
                                                 const float* __restrict__ mask,
                                                 const float* __restrict__ proto) {
    __shared__ float As[128][33];   // [b_local][k_local]  16.9 KB
    __shared__ float Ws[32][66];    // [k_local][p] pitch 66 (8B-aligned rows)
    int ks = blockIdx.x;            // 0..63
    int k0 = ks * 64;
    int b0 = blockIdx.y * 128;
    int tid = threadIdx.x;
    int warp = tid >> 5;            // 0..7
    int lane = tid & 31;

    unsigned long long acc2[4][4];
    #pragma unroll
    for (int j = 0; j < 4; j++)
        #pragma unroll
        for (int i = 0; i < 4; i++) acc2[j][i] = 0ull;
    float x2a[4] = {0.f, 0.f, 0.f, 0.f};

    for (int h = 0; h < 2; h++) {
        int kh = k0 + h * 32;
        int k = kh + lane;
        bool isx = (k < KK);
        bool ism = (!isx) && (k < KREAL);
        int t = isx ? (k / CC) : (k - KK);
        if (h) __syncthreads();

        // stage A half: 128 rows x 32 cols (16 rows per thread)
        #pragma unroll
        for (int i = 0; i < 16; i++) {
            int brow = warp + i * 8;
            int b = b0 + brow;
            float v = 0.0f;
            if (isx)      v = x[b * KK + k] * __ldg(&mask[b * TT + t]);
            else if (ism) v = __ldg(&mask[b * TT + t]);
            As[brow][lane] = v;
        }
        // stage W half straight from proto: warp handles p = warp*8 .. +7
        #pragma unroll
        for (int i = 0; i < 8; i++) {
            int p = warp * 8 + i;
            float wv = 0.0f;
            if (isx) {
                wv = -2.0f * __ldg(&proto[p * KK + k]);
            } else if (ism) {
                float s = 0.0f;
                const float* pb = proto + p * KK + t * CC;
                #pragma unroll
                for (int c = 0; c < CC; c++) { float q = __ldg(&pb[c]); s += q * q; }
                wv = s;
            }
            Ws[lane][p] = wv;       // transposed store, pitch 66 -> 2-way max
        }
        __syncthreads();

        #pragma unroll 8
        for (int kk = 0; kk < 32; kk++) {
            float a[4];
            #pragma unroll
            for (int j = 0; j < 4; j++) a[j] = As[lane + 32 * j][kk];
            const unsigned long long* wp =
                reinterpret_cast<const unsigned long long*>(&Ws[kk][warp * 8]);
            unsigned long long w0 = wp[0], w1 = wp[1], w2 = wp[2], w3 = wp[3];
            #pragma unroll
            for (int j = 0; j < 4; j++) {
                unsigned long long aj = pack2(a[j]);
                fma2(acc2[j][0], aj, w0);
                fma2(acc2[j][1], aj, w1);
                fma2(acc2[j][2], aj, w2);
                fma2(acc2[j][3], aj, w3);
            }
            if (warp == 0 && (kh + kk) < KK) {
                #pragma unroll
                for (int j = 0; j < 4; j++) x2a[j] += a[j] * a[j];
            }
        }
    }

    // write partials
    #pragma unroll
    for (int j = 0; j < 4; j++) {
        int b = b0 + lane + 32 * j;
        float2 p0v = *reinterpret_cast<float2*>(&acc2[j][0]);
        float2 p1v = *reinterpret_cast<float2*>(&acc2[j][1]);
        float2 p2v = *reinterpret_cast<float2*>(&acc2[j][2]);
        float2 p3v = *reinterpret_cast<float2*>(&acc2[j][3]);
        float* dst = &g_part[(ks * BB + b) * PP + warp * 8];
        *reinterpret_cast<float4*>(dst)     = make_float4(p0v.x, p0v.y, p1v.x, p1v.y);
        *reinterpret_cast<float4*>(dst + 4) = make_float4(p2v.x, p2v.y, p3v.x, p3v.y);
    }
    if (warp == 0) {
        #pragma unroll
        for (int j = 0; j < 4; j++)
            g_x2p[(b0 + lane + 32 * j) * NKS + ks] = x2a[j];
    }
}

// ---------------- flat float4 pass-through copies ---------------------------
#define FLAT_X4   467200               // BB*KK/4
#define FLAT_M4   46720                // BB*TT/4
#define FLAT_TOT  (FLAT_X4 + FLAT_M4)

__global__ void __launch_bounds__(256) k_copy(const float* __restrict__ x,
                                              const float* __restrict__ mask,
                                              float* __restrict__ out) {
    const float4* xs = reinterpret_cast<const float4*>(x);
    const float4* ms = reinterpret_cast<const float4*>(mask);
    float4* dx = reinterpret_cast<float4*>(out + O_INSEQ);
    float4* dm = reinterpret_cast<float4*>(out + O_MASK);
    int stride = gridDim.x * 256;
    for (int i = blockIdx.x * 256 + threadIdx.x; i < FLAT_TOT; i += stride) {
        if (i < FLAT_X4) dx[i] = xs[i];
        else             dm[i - FLAT_X4] = ms[i - FLAT_X4];
    }
}

// ---------------- reduce + argmin + dist/idx/label + gather ----------------
__global__ void __launch_bounds__(256) k_reduce(const int* __restrict__ label,
                                                const float* __restrict__ proto,
                                                float* __restrict__ out) {
    __shared__ float sp[4][64];
    __shared__ float sx0;
    __shared__ float sv[64];
    __shared__ int si[64];
    __shared__ int sidx;
    int b = blockIdx.x;
    int tid = threadIdx.x;
    int pp = tid & 63;
    int g = tid >> 6;                  // 0..3: each sums 16 ks chunks

    float acc = 0.0f;
    #pragma unroll
    for (int i = 0; i < 16; i++)
        acc += g_part[((g * 16 + i) * BB + b) * PP + pp];
    sp[g][pp] = acc;

    if (tid < 32) {                    // x2 = sum of 64 chunk partials
        float v = g_x2p[b * NKS + tid] + g_x2p[b * NKS + 32 + tid];
        #pragma unroll
        for (int s = 16; s > 0; s >>= 1)
            v += __shfl_xor_sync(0xffffffff, v, s);
        if (tid == 0) sx0 = v;
    }
    __syncthreads();

    if (tid < 64) {
        float tot = sp[0][pp] + sp[1][pp] + sp[2][pp] + sp[3][pp] + sx0;
        out[O_DIST + b * PP + pp] = tot;
        sv[pp] = tot;
        si[pp] = pp;
    }
    __syncthreads();
    for (int s = 32; s > 0; s >>= 1) {
        if (tid < s) {
            float ov = sv[tid + s];
            int oi = si[tid + s];
            if (ov < sv[tid] || (ov == sv[tid] && oi < si[tid])) {
                sv[tid] = ov;
                si[tid] = oi;
            }
        }
        __syncthreads();
    }
    if (tid == 0) {
        sidx = si[0];
        out[O_IDX + b] = (float)si[0];
        out[O_LABEL + b] = (float)label[b];
    }
    __syncthreads();

    // gather selected prototype row (8B-aligned rows -> float2)
    int idx = sidx;
    const float2* src = reinterpret_cast<const float2*>(proto + idx * KK);
    float2* d0 = reinterpret_cast<float2*>(out + O_OUTSEQ + b * KK);
    #pragma unroll 4
    for (int i = tid; i < KK / 2; i += 256)
        d0[i] = src[i];
}

// ---------------- launcher --------------------------------------------------
extern "C" void kernel_launch(void* const* d_in, const int* in_sizes, int n_in,
                              void* d_out, int out_size) {
    const float* x     = (const float*)d_in[0];  // [B,T,C]
    const float* mask  = (const float*)d_in[1];  // [B,T]
    const int*   label = (const int*)d_in[2];    // [B]
    const float* proto = (const float*)d_in[3];  // [P,T,C]
    float* out = (float*)d_out;

    k_gemm<<<dim3(NKS, 4), 256>>>(x, mask, proto);
    k_copy<<<448, 256>>>(x, mask, out);
    k_reduce<<<BB, 256>>>(label, proto, out);
}

// round 7
// speedup vs baseline: 1.3877x; 1.0738x over previous
#include <cuda_runtime.h>
#include <cuda_bf16.h>
#include <cstdint>

// Problem constants
#define BB 512      // batch
#define TT 365      // time steps
#define CC 10       // channels
#define PP 64       // prototypes
#define KK 3650     // T*C  (even!)
#define KREAL 4015  // 3650 + 365
#define NKS 64      // K-split chunks (64 deep each)

// Output layout (float32, concatenated in reference return order)
#define O_OUTSEQ 0
#define O_INSEQ  1868800
#define O_DIST   3737600
#define O_IDX    3770368
#define O_LABEL  3770880
#define O_MASK   3771392

// ---------------- scratch ---------------------------------------------------
__device__ float g_part[NKS * BB * PP];     // [ks][b][p] (8 MB)
__device__ float g_x2p[BB * NKS];           // x2 partials [b][ks]

// ---------------- packed f32x2 helpers -------------------------------------
__device__ __forceinline__ void fma2(unsigned long long& d,
                                     unsigned long long a,
                                     unsigned long long b) {
    asm("fma.rn.f32x2 %0, %1, %2, %0;" : "+l"(d) : "l"(a), "l"(b));
}
__device__ __forceinline__ unsigned long long pack2(float x) {
    unsigned long long r;
    asm("mov.b64 %0, {%1, %1};" : "=l"(r) : "f"(x));
    return r;
}

// ---------------- fused GEMM ------------------------------------------------
// BM=64 (b), BN=64 (all p), chunk=64 (2 halves of 32), 256 threads.
// grid (NKS=64, 8) = 512 blocks for occupancy.
// Thread (tb=tid&15, tp=tid>>4): outputs b = tb+16j (j<4), p = 4*tp..+3.
__global__ void __launch_bounds__(256, 3) k_gemm(const float* __restrict__ x,
                                                 const float* __restrict__ mask,
                                                 const float* __restrict__ proto) {
    __shared__ float As[64][34];    // [b_local][k_local]  8.7 KB (pitch even)
    __shared__ float Ws[32][66];    // [k_local][p]        8.4 KB (pitch even)
    int ks = blockIdx.x;            // 0..63
    int k0 = ks * 64;
    int b0 = blockIdx.y * 64;
    int tid = threadIdx.x;
    int tb = tid & 15;
    int tp = tid >> 4;              // 0..15
    int kk2 = tid & 15;             // staging: float2 index (32 k per half)
    int rr  = tid >> 4;             // staging: row group 0..15

    unsigned long long acc2[4][2];
    #pragma unroll
    for (int j = 0; j < 4; j++) { acc2[j][0] = 0ull; acc2[j][1] = 0ull; }
    float x2a[4] = {0.f, 0.f, 0.f, 0.f};

    for (int h = 0; h < 2; h++) {
        int kh = k0 + h * 32;
        int k = kh + kk2 * 2;           // even; pair (k, k+1) never straddles KK
        bool isx = (k < KK);
        int t0 = isx ? (k / CC) : (k - KK);
        int t1 = isx ? ((k + 1) / CC) : (k + 1 - KK);
        if (h) __syncthreads();

        // ---- stage A half: 64 rows x 32 k, float2 per thread x 4 passes ---
        #pragma unroll
        for (int pass = 0; pass < 4; pass++) {
            int brow = rr + 16 * pass;
            int b = b0 + brow;
            float2 v;
            if (isx) {
                float2 xv = *reinterpret_cast<const float2*>(&x[b * KK + k]);
                v.x = xv.x * __ldg(&mask[b * TT + t0]);
                v.y = xv.y * __ldg(&mask[b * TT + t1]);
            } else {
                v.x = (k     < KREAL) ? __ldg(&mask[b * TT + t0]) : 0.0f;
                v.y = (k + 1 < KREAL) ? __ldg(&mask[b * TT + t1]) : 0.0f;
            }
            *reinterpret_cast<float2*>(&As[brow][kk2 * 2]) = v;
        }
        // ---- stage W half: 32 k x 64 p, float2 per thread x 4 passes ------
        #pragma unroll
        for (int pass = 0; pass < 4; pass++) {
            int p = rr + 16 * pass;
            float2 wv;
            if (isx) {
                float2 pv = *reinterpret_cast<const float2*>(&proto[p * KK + k]);
                wv.x = -2.0f * pv.x;
                wv.y = -2.0f * pv.y;
            } else {
                wv.x = 0.0f; wv.y = 0.0f;
                if (k < KREAL) {
                    float s = 0.0f;
                    const float* pb = proto + p * KK + t0 * CC;
                    #pragma unroll
                    for (int c = 0; c < CC; c++) { float q = pb[c]; s += q * q; }
                    wv.x = s;
                }
                if (k + 1 < KREAL) {
                    float s = 0.0f;
                    const float* pb = proto + p * KK + t1 * CC;
                    #pragma unroll
                    for (int c = 0; c < CC; c++) { float q = pb[c]; s += q * q; }
                    wv.y = s;
                }
            }
            Ws[kk2 * 2][p]     = wv.x;
            Ws[kk2 * 2 + 1][p] = wv.y;
        }
        __syncthreads();

        // ---- compute 32-deep -------------------------------------------------
        #pragma unroll 8
        for (int kk = 0; kk < 32; kk++) {
            float a[4];
            #pragma unroll
            for (int j = 0; j < 4; j++) a[j] = As[tb + 16 * j][kk];
            const unsigned long long* wp =
                reinterpret_cast<const unsigned long long*>(&Ws[kk][tp * 4]);
            unsigned long long w01 = wp[0], w23 = wp[1];
            #pragma unroll
            for (int j = 0; j < 4; j++) {
                unsigned long long aj = pack2(a[j]);
                fma2(acc2[j][0], aj, w01);
                fma2(acc2[j][1], aj, w23);
            }
            if (tp == 0 && (kh + kk) < KK) {
                #pragma unroll
                for (int j = 0; j < 4; j++) x2a[j] += a[j] * a[j];
            }
        }
    }

    // ---- write partials -----------------------------------------------------
    #pragma unroll
    for (int j = 0; j < 4; j++) {
        int b = b0 + tb + 16 * j;
        float2 v0 = *reinterpret_cast<float2*>(&acc2[j][0]);
        float2 v1 = *reinterpret_cast<float2*>(&acc2[j][1]);
        *reinterpret_cast<float4*>(&g_part[(ks * BB + b) * PP + tp * 4]) =
            make_float4(v0.x, v0.y, v1.x, v1.y);
    }
    if (tp == 0) {
        #pragma unroll
        for (int j = 0; j < 4; j++)
            g_x2p[(b0 + tb + 16 * j) * NKS + ks] = x2a[j];
    }
}

// ---------------- flat float4 pass-through copies ---------------------------
#define FLAT_X4   467200               // BB*KK/4
#define FLAT_M4   46720                // BB*TT/4
#define FLAT_TOT  (FLAT_X4 + FLAT_M4)

__global__ void __launch_bounds__(256) k_copy(const float* __restrict__ x,
                                              const float* __restrict__ mask,
                                              float* __restrict__ out) {
    const float4* xs = reinterpret_cast<const float4*>(x);
    const float4* ms = reinterpret_cast<const float4*>(mask);
    float4* dx = reinterpret_cast<float4*>(out + O_INSEQ);
    float4* dm = reinterpret_cast<float4*>(out + O_MASK);
    int stride = gridDim.x * 256;
    for (int i = blockIdx.x * 256 + threadIdx.x; i < FLAT_TOT; i += stride) {
        if (i < FLAT_X4) dx[i] = xs[i];
        else             dm[i - FLAT_X4] = ms[i - FLAT_X4];
    }
}

// ---------------- reduce + argmin + dist/idx/label + gather ----------------
__global__ void __launch_bounds__(256) k_reduce(const int* __restrict__ label,
                                                const float* __restrict__ proto,
                                                float* __restrict__ out) {
    __shared__ float sp[4][64];
    __shared__ float sx0;
    __shared__ float sv[64];
    __shared__ int si[64];
    __shared__ int sidx;
    int b = blockIdx.x;
    int tid = threadIdx.x;
    int pp = tid & 63;
    int g = tid >> 6;                  // 0..3: each sums 16 ks chunks

    float acc = 0.0f;
    #pragma unroll
    for (int i = 0; i < 16; i++)
        acc += g_part[((g * 16 + i) * BB + b) * PP + pp];
    sp[g][pp] = acc;

    if (tid < 32) {                    // x2 = sum of 64 chunk partials
        float v = g_x2p[b * NKS + tid] + g_x2p[b * NKS + 32 + tid];
        #pragma unroll
        for (int s = 16; s > 0; s >>= 1)
            v += __shfl_xor_sync(0xffffffff, v, s);
        if (tid == 0) sx0 = v;
    }
    __syncthreads();

    if (tid < 64) {
        float tot = sp[0][pp] + sp[1][pp] + sp[2][pp] + sp[3][pp] + sx0;
        out[O_DIST + b * PP + pp] = tot;
        sv[pp] = tot;
        si[pp] = pp;
    }
    __syncthreads();
    for (int s = 32; s > 0; s >>= 1) {
        if (tid < s) {
            float ov = sv[tid + s];
            int oi = si[tid + s];
            if (ov < sv[tid] || (ov == sv[tid] && oi < si[tid])) {
                sv[tid] = ov;
                si[tid] = oi;
            }
        }
        __syncthreads();
    }
    if (tid == 0) {
        sidx = si[0];
        out[O_IDX + b] = (float)si[0];
        out[O_LABEL + b] = (float)label[b];
    }
    __syncthreads();

    // gather selected prototype row (8B-aligned rows -> float2)
    int idx = sidx;
    const float2* src = reinterpret_cast<const float2*>(proto + idx * KK);
    float2* d0 = reinterpret_cast<float2*>(out + O_OUTSEQ + b * KK);
    #pragma unroll 4
    for (int i = tid; i < KK / 2; i += 256)
        d0[i] = src[i];
}

// ---------------- launcher --------------------------------------------------
extern "C" void kernel_launch(void* const* d_in, const int* in_sizes, int n_in,
                              void* d_out, int out_size) {
    const float* x     = (const float*)d_in[0];  // [B,T,C]
    const float* mask  = (const float*)d_in[1];  // [B,T]
    const int*   label = (const int*)d_in[2];    // [B]
    const float* proto = (const float*)d_in[3];  // [P,T,C]
    float* out = (float*)d_out;

    k_gemm<<<dim3(NKS, 8), 256>>>(x, mask, proto);
    k_copy<<<448, 256>>>(x, mask, out);
    k_reduce<<<BB, 256>>>(label, proto, out);
}